// round 1
// baseline (speedup 1.0000x reference)
#include <cuda_runtime.h>
#include <math.h>

// Problem constants (fixed by the dataset generator)
#define EDIM 128
#define FCH  64
#define WW   126           // EDIM - 2
#define A2   3             // arity - 2
#define NCOLS 10           // x_batch columns
#define NTASK 216          // 45 C1 + 9 S1 + 3*(45 C2 + 9 S2)
#define GB   4             // batch rows per block in main kernel

// Global accumulators / derived BN params (device globals: no allocs allowed)
__device__ double g_acc[NTASK];
__device__ float2 g_sb1[FCH];          // (scale, bias) for conv1 BN per channel
__device__ float2 g_sb2[A2][FCH];      // per (a, f)

// ---------------------------------------------------------------------------
// Kernel 0: zero the fp64 accumulators (graph replays must be deterministic)
// ---------------------------------------------------------------------------
__global__ void zero_kernel() {
    int t = threadIdx.x;
    if (t < NTASK) g_acc[t] = 0.0;
}

// ---------------------------------------------------------------------------
// Kernel 1: per-row tap sums S and tap correlations C, reduced via fp64 atomics
// Row layout in smem: 0=E0, 1=R, 2=E1, 3=HT0, 4=TT0, 5=HT1, 6=TT1, 7=HT2, 8=TT2
// conv1 rows (i=0,1,2) -> smem {0,1,2};  conv2[a] rows -> {3+2a, 1, 4+2a}
// ---------------------------------------------------------------------------
__global__ void __launch_bounds__(256) stats_kernel(
    const int* __restrict__ xb,
    const float* __restrict__ er,
    const float* __restrict__ ee,
    const float* __restrict__ et)
{
    __shared__ float s[9][EDIM];
    __shared__ const float* rp[9];

    int b = blockIdx.x;
    int tid = threadIdx.x;

    if (tid < 9) {
        const int* x = xb + b * NCOLS;
        const float* p;
        switch (tid) {
            case 0: p = ee + (size_t)x[1] * EDIM; break;
            case 1: p = er + (size_t)x[0] * EDIM; break;
            case 2: p = ee + (size_t)x[3] * EDIM; break;
            default: p = et + (size_t)x[tid + 1] * EDIM; break; // rows 3..8 -> x[4..9]
        }
        rp[tid] = p;
    }
    __syncthreads();

    for (int i = tid; i < 9 * EDIM; i += 256) {
        int r = i >> 7, c = i & 127;
        s[r][c] = __ldg(rp[r] + c);
    }
    __syncthreads();

    int t = tid;
    if (t >= NTASK) return;

    // decode task
    int kind, a = 0, k;
    if (t < 45)      { kind = 0; k = t; }
    else if (t < 54) { kind = 1; k = t - 45; }
    else {
        int u = t - 54; a = u / 54; u %= 54;
        if (u < 45) { kind = 2; k = u; }
        else        { kind = 3; k = u - 45; }
    }

    float acc = 0.f;
    if (kind == 0 || kind == 2) {
        // triangular (p<=q) unpack
        int p = 0;
        while (k >= 9 - p) { k -= 9 - p; p++; }
        int q = p + k;
        int i1 = p / 3, j1 = p % 3, i2 = q / 3, j2 = q % 3;
        int r1, r2;
        if (kind == 0) { r1 = i1; r2 = i2; }
        else {
            r1 = (i1 == 1) ? 1 : (i1 == 0 ? 3 + 2 * a : 4 + 2 * a);
            r2 = (i2 == 1) ? 1 : (i2 == 0 ? 3 + 2 * a : 4 + 2 * a);
        }
        #pragma unroll 7
        for (int w = 0; w < WW; w++) acc += s[r1][w + j1] * s[r2][w + j2];
    } else {
        int i1 = k / 3, j1 = k % 3;
        int r1 = (kind == 1) ? i1
                             : ((i1 == 1) ? 1 : (i1 == 0 ? 3 + 2 * a : 4 + 2 * a));
        #pragma unroll 7
        for (int w = 0; w < WW; w++) acc += s[r1][w + j1];
    }
    atomicAdd(&g_acc[t], (double)acc);
}

// ---------------------------------------------------------------------------
// Kernel 2: finalize per-channel BN scale/bias.
//   mean_f = (W_f . S)/N ;  E[c^2]_f = (W_f^T C W_f)/N ;  var = E[c^2]-mean^2
//   scale = gamma * rsqrt(var+eps) ; bias = beta - mean*scale
// ---------------------------------------------------------------------------
__global__ void finalize_kernel(
    const float* __restrict__ c1w, const float* __restrict__ g1, const float* __restrict__ be1,
    const float* __restrict__ c2w, const float* __restrict__ g2, const float* __restrict__ be2,
    int B)
{
    int t = threadIdx.x;
    double N = (double)B * (double)WW;
    if (t >= FCH + A2 * FCH) return;

    const double* Cm;
    const double* Sm;
    const float*  wf;
    float gamma, beta;
    int f;
    int a = -1;
    if (t < FCH) {
        f = t;
        Cm = g_acc;        Sm = g_acc + 45;
        wf = c1w + f * 9;  gamma = g1[f]; beta = be1[f];
    } else {
        int u = t - FCH; a = u / FCH; f = u % FCH;
        const double* base = g_acc + 54 + a * 54;
        Cm = base;         Sm = base + 45;
        wf = c2w + f * 9;  gamma = g2[f]; beta = be2[f];
    }

    double wd[9];
    #pragma unroll
    for (int p = 0; p < 9; p++) wd[p] = (double)wf[p];

    double mean = 0.0;
    #pragma unroll
    for (int p = 0; p < 9; p++) mean += wd[p] * Sm[p];
    mean /= N;

    double ex2 = 0.0;
    #pragma unroll
    for (int p = 0; p < 9; p++) {
        #pragma unroll
        for (int q = 0; q < 9; q++) {
            int pp = p < q ? p : q;
            int qq = p < q ? q : p;
            int idx = pp * 9 - (pp * (pp - 1)) / 2 + (qq - pp);
            ex2 += wd[p] * wd[q] * Cm[idx];
        }
    }
    ex2 /= N;

    double var = ex2 - mean * mean;
    double rinv = 1.0 / sqrt(var + 1e-5);
    float sc = (float)((double)gamma * rinv);
    float bi = (float)((double)beta - mean * (double)gamma * rinv);
    if (a < 0) g_sb1[f] = make_float2(sc, bi);
    else       g_sb2[a][f] = make_float2(sc, bi);
}

// ---------------------------------------------------------------------------
// Kernel 3: fused conv -> BN -> relu -> min -> FC dot, 4 batch rows per block.
// thread = width position w (0..125); f-loop in registers; warp-shuffle reduce.
// ---------------------------------------------------------------------------
__global__ void __launch_bounds__(128) main_kernel(
    const int* __restrict__ xb,
    const float* __restrict__ er, const float* __restrict__ ee, const float* __restrict__ et,
    const float* __restrict__ c1w, const float* __restrict__ c2w,
    const float* __restrict__ fcn_w, const float* __restrict__ fcn_b,
    float* __restrict__ out, int B)
{
    __shared__ float rows[GB][9][EDIM];
    __shared__ __align__(16) float w1s[FCH][12];
    __shared__ __align__(16) float w2s[FCH][12];
    __shared__ float2 sb1[FCH];
    __shared__ float2 sb2[A2][FCH];
    __shared__ const float* rp[GB][9];
    __shared__ float red[4][GB];

    int tid = threadIdx.x;
    int b0 = blockIdx.x * GB;

    if (tid < GB * 9) {
        int g = tid / 9, r = tid % 9;
        int b = b0 + g;
        const float* p = ee;  // dummy for OOB guard
        if (b < B) {
            const int* x = xb + b * NCOLS;
            switch (r) {
                case 0: p = ee + (size_t)x[1] * EDIM; break;
                case 1: p = er + (size_t)x[0] * EDIM; break;
                case 2: p = ee + (size_t)x[3] * EDIM; break;
                default: p = et + (size_t)x[r + 1] * EDIM; break;
            }
        }
        rp[g][r] = p;
    }
    __syncthreads();

    // gather 36 embedding rows, coalesced: one row (128 floats) per iteration
    for (int i = tid; i < GB * 9 * EDIM; i += 128) {
        int g = i / (9 * EDIM);
        int rem = i % (9 * EDIM);
        int r = rem >> 7, c = rem & 127;
        rows[g][r][c] = __ldg(rp[g][r] + c);
    }
    // conv weights (padded to 12 floats/channel for float4 broadcast loads)
    for (int i = tid; i < FCH * 9; i += 128) {
        w1s[i / 9][i % 9] = c1w[i];
        w2s[i / 9][i % 9] = c2w[i];
    }
    if (tid < FCH) sb1[tid] = g_sb1[tid];
    for (int i = tid; i < A2 * FCH; i += 128) sb2[i / FCH][i % FCH] = g_sb2[i / FCH][i % FCH];
    __syncthreads();

    float acc[GB] = {0.f, 0.f, 0.f, 0.f};
    int w = tid;
    const float* fcn1 = fcn_w;
    const float* fcn2 = fcn_w + FCH * WW;

    if (w < WW) {
        #pragma unroll
        for (int g = 0; g < GB; g++) {
            if (b0 + g >= B) break;
            // register windows (27 values; R row shared between branches)
            float e00 = rows[g][0][w], e01 = rows[g][0][w + 1], e02 = rows[g][0][w + 2];
            float r0  = rows[g][1][w], r1  = rows[g][1][w + 1], r2  = rows[g][1][w + 2];
            float e10 = rows[g][2][w], e11 = rows[g][2][w + 1], e12 = rows[g][2][w + 2];
            float ht[A2][3], tt[A2][3];
            #pragma unroll
            for (int a = 0; a < A2; a++) {
                #pragma unroll
                for (int j = 0; j < 3; j++) {
                    ht[a][j] = rows[g][3 + 2 * a][w + j];
                    tt[a][j] = rows[g][4 + 2 * a][w + j];
                }
            }
            float a_ = 0.f;
            #pragma unroll 4
            for (int f = 0; f < FCH; f++) {
                const float4* wp = (const float4*)&w1s[f][0];
                float4 A = wp[0], Bv = wp[1];
                float w8 = w1s[f][8];
                float c1 = fmaf(A.x, e00, fmaf(A.y, e01, fmaf(A.z, e02,
                           fmaf(A.w, r0,  fmaf(Bv.x, r1, fmaf(Bv.y, r2,
                           fmaf(Bv.z, e10, fmaf(Bv.w, e11, w8 * e12))))))));
                float2 sA = sb1[f];
                float v1 = fmaxf(fmaf(c1, sA.x, sA.y), 0.f);
                a_ = fmaf(v1, __ldg(&fcn1[f * WW + w]), a_);

                const float4* wq = (const float4*)&w2s[f][0];
                float4 C = wq[0], D = wq[1];
                float q8 = w2s[f][8];
                float m = 3.0e38f;
                #pragma unroll
                for (int a = 0; a < A2; a++) {
                    float c2 = fmaf(C.x, ht[a][0], fmaf(C.y, ht[a][1], fmaf(C.z, ht[a][2],
                               fmaf(C.w, r0,  fmaf(D.x, r1, fmaf(D.y, r2,
                               fmaf(D.z, tt[a][0], fmaf(D.w, tt[a][1], q8 * tt[a][2]))))))));
                    float2 sB = sb2[a][f];
                    float v = fmaf(c2, sB.x, sB.y);
                    m = fminf(m, v);
                }
                m = fmaxf(m, 0.f);
                a_ = fmaf(m, __ldg(&fcn2[f * WW + w]), a_);
            }
            acc[g] = a_;
        }
    }

    // block reduction: warp shuffles then cross-warp via smem
    int lane = tid & 31, warp = tid >> 5;
    #pragma unroll
    for (int g = 0; g < GB; g++) {
        float v = acc[g];
        #pragma unroll
        for (int off = 16; off; off >>= 1) v += __shfl_down_sync(0xffffffffu, v, off);
        if (lane == 0) red[warp][g] = v;
    }
    __syncthreads();
    if (tid < GB && b0 + tid < B) {
        float tot = red[0][tid] + red[1][tid] + red[2][tid] + red[3][tid] + __ldg(&fcn_b[0]);
        out[b0 + tid] = tot;
    }
}

// ---------------------------------------------------------------------------
// Launch: zero -> stats -> finalize -> main (all graph-capturable)
// Input order: x_batch, arity, mode, emb_relations, emb_entities, emb_types,
//   conv1_w, conv1_b, bn1_gamma, bn1_beta, conv2_w, conv2_b, bn2_gamma,
//   bn2_beta, fcn_w, fcn_b
// ---------------------------------------------------------------------------
extern "C" void kernel_launch(void* const* d_in, const int* in_sizes, int n_in,
                              void* d_out, int out_size)
{
    const int*   xb  = (const int*)d_in[0];
    const float* er  = (const float*)d_in[3];
    const float* ee  = (const float*)d_in[4];
    const float* et  = (const float*)d_in[5];
    const float* c1w = (const float*)d_in[6];
    const float* g1  = (const float*)d_in[8];
    const float* be1 = (const float*)d_in[9];
    const float* c2w = (const float*)d_in[10];
    const float* g2  = (const float*)d_in[12];
    const float* be2 = (const float*)d_in[13];
    const float* fw  = (const float*)d_in[14];
    const float* fb  = (const float*)d_in[15];

    int B = in_sizes[0] / NCOLS;

    zero_kernel<<<1, 256>>>();
    stats_kernel<<<B, 256>>>(xb, er, ee, et);
    finalize_kernel<<<1, 256>>>(c1w, g1, be1, c2w, g2, be2, B);
    main_kernel<<<(B + GB - 1) / GB, 128>>>(xb, er, ee, et, c1w, c2w, fw, fb,
                                            (float*)d_out, B);
}

// round 3
// speedup vs baseline: 1.6319x; 1.6319x over previous
#include <cuda_runtime.h>
#include <math.h>

// Problem constants (fixed by the dataset generator)
#define EDIM 128
#define FCH  64
#define WW   126           // EDIM - 2
#define A2   3             // arity - 2
#define NCOLS 10           // x_batch columns
#define NTASK 216          // 45 C1 + 9 S1 + 3*(45 C2 + 9 S2)
#define GB   4             // batch rows per block in main kernel
#define SR   32            // batch rows per stats block
#define MAXPART 512

typedef unsigned long long u64;

// ---- f32x2 packed helpers (Blackwell packed fp32) ----
__device__ __forceinline__ u64 pk(float a, float b) {
    u64 d; asm("mov.b64 %0, {%1,%2};" : "=l"(d) : "f"(a), "f"(b)); return d;
}
__device__ __forceinline__ void upk(u64 d, float& a, float& b) {
    asm("mov.b64 {%0,%1}, %2;" : "=f"(a), "=f"(b) : "l"(d));
}
__device__ __forceinline__ u64 fma2(u64 a, u64 b, u64 c) {
    u64 d; asm("fma.rn.f32x2 %0, %1, %2, %3;" : "=l"(d) : "l"(a), "l"(b), "l"(c)); return d;
}
__device__ __forceinline__ u64 mul2(u64 a, u64 b) {
    u64 d; asm("mul.rn.f32x2 %0, %1, %2;" : "=l"(d) : "l"(a), "l"(b)); return d;
}

// Global scratch (device globals: no allocs allowed)
__device__ float  g_part[MAXPART][NTASK];
__device__ double g_acc[NTASK];
__device__ float2 g_sb1[FCH];
__device__ float2 g_sb2[A2][FCH];

// ---------------------------------------------------------------------------
// Kernel 1: tap sums S / correlations C.
// Block = 32 batch rows, 256 threads = 8 warps.
//   warp -> (branch wq = warp&3, w-half = warp>>2).  Branch wq uses rows
//   (top,mid,bot): wq==0 -> (0,1,2) [conv1], else (2wq+1, 1, 2wq+2) [conv2].
// Each thread accumulates all 54 branch tasks in fp32 registers across its
// 2 w-positions x 32 rows; warp-shuffle reduce; fp32 partial -> g_part.
// Fully deterministic (no atomics).
// ---------------------------------------------------------------------------
__global__ void __launch_bounds__(256) stats_kernel(
    const int* __restrict__ xb,
    const float* __restrict__ er,
    const float* __restrict__ ee,
    const float* __restrict__ et,
    int B)
{
    __shared__ float s[9][EDIM];
    __shared__ const float* rp[SR][9];

    int tid = threadIdx.x;
    int warp = tid >> 5, lane = tid & 31;
    int wq = warp & 3, whalf = warp >> 2;
    int b0 = blockIdx.x * SR;

    // precompute all 32x9 row pointers; OOB rows -> index 0 (embedding row 0
    // is all-zero by construction, and zero rows contribute 0 to all stats)
    for (int i = tid; i < SR * 9; i += 256) {
        int g = i / 9, r = i % 9;
        int b = b0 + g;
        const float* p;
        if (b < B) {
            const int* x = xb + (size_t)b * NCOLS;
            switch (r) {
                case 0: p = ee + (size_t)x[1] * EDIM; break;
                case 1: p = er + (size_t)x[0] * EDIM; break;
                case 2: p = ee + (size_t)x[3] * EDIM; break;
                default: p = et + (size_t)x[r + 1] * EDIM; break;
            }
        } else {
            p = (r == 0 || r == 2) ? ee : (r == 1 ? er : et);  // row 0 = zeros
        }
        rp[g][r] = p;
    }

    int rt = (wq == 0) ? 0 : 2 * wq + 1;
    int rb = (wq == 0) ? 2 : 2 * wq + 2;

    float facc[54];
    #pragma unroll
    for (int k = 0; k < 54; k++) facc[k] = 0.f;

    __syncthreads();
    for (int g = 0; g < SR; g++) {
        // load one 9-row set (coalesced, no divergence)
        for (int i = tid; i < 9 * EDIM; i += 256) {
            int r = i >> 7, c = i & 127;
            s[r][c] = __ldg(rp[g][r] + c);
        }
        __syncthreads();

        #pragma unroll
        for (int ch = 0; ch < 2; ch++) {
            int w = whalf * 64 + ch * 32 + lane;
            if (w < WW) {
                float v[9];
                #pragma unroll
                for (int j = 0; j < 3; j++) {
                    v[j]     = s[rt][w + j];
                    v[3 + j] = s[1][w + j];
                    v[6 + j] = s[rb][w + j];
                }
                int idx = 0;
                #pragma unroll
                for (int p = 0; p < 9; p++) {
                    facc[45 + p] += v[p];
                    #pragma unroll
                    for (int q = p; q < 9; q++) { facc[idx] += v[p] * v[q]; idx++; }
                }
            }
        }
        __syncthreads();
    }

    // warp-shuffle reduce each accumulator
    #pragma unroll
    for (int k = 0; k < 54; k++) {
        float v = facc[k];
        #pragma unroll
        for (int off = 16; off; off >>= 1) v += __shfl_down_sync(0xffffffffu, v, off);
        facc[k] = v;
    }
    if (lane == 0) {
        int part = blockIdx.x * 2 + whalf;
        #pragma unroll
        for (int k = 0; k < 54; k++) g_part[part][wq * 54 + k] = facc[k];
    }
}

// ---------------------------------------------------------------------------
// Kernel 2: deterministic reduce of partials into fp64 g_acc
// ---------------------------------------------------------------------------
__global__ void reduce_kernel(int nparts) {
    int t = threadIdx.x;
    if (t >= NTASK) return;
    double acc = 0.0;
    for (int p = 0; p < nparts; p++) acc += (double)g_part[p][t];
    g_acc[t] = acc;
}

// ---------------------------------------------------------------------------
// Kernel 3: finalize per-channel BN scale/bias.
//   mean_f = (W_f . S)/N ;  E[c^2]_f = (W_f^T C W_f)/N ;  var = E[c^2]-mean^2
//   scale = gamma * rsqrt(var+eps) ; bias = beta - mean*scale
// ---------------------------------------------------------------------------
__global__ void finalize_kernel(
    const float* __restrict__ c1w, const float* __restrict__ g1, const float* __restrict__ be1,
    const float* __restrict__ c2w, const float* __restrict__ g2, const float* __restrict__ be2,
    int B)
{
    int t = threadIdx.x;
    double N = (double)B * (double)WW;
    if (t >= FCH + A2 * FCH) return;

    const double* Cm; const double* Sm; const float* wf;
    float gamma, beta; int f; int a = -1;
    if (t < FCH) {
        f = t; Cm = g_acc; Sm = g_acc + 45;
        wf = c1w + f * 9; gamma = g1[f]; beta = be1[f];
    } else {
        int u = t - FCH; a = u / FCH; f = u % FCH;
        const double* base = g_acc + 54 + a * 54;
        Cm = base; Sm = base + 45;
        wf = c2w + f * 9; gamma = g2[f]; beta = be2[f];
    }

    double wd[9];
    #pragma unroll
    for (int p = 0; p < 9; p++) wd[p] = (double)wf[p];

    double mean = 0.0;
    #pragma unroll
    for (int p = 0; p < 9; p++) mean += wd[p] * Sm[p];
    mean /= N;

    double ex2 = 0.0;
    #pragma unroll
    for (int p = 0; p < 9; p++) {
        #pragma unroll
        for (int q = 0; q < 9; q++) {
            int pp = p < q ? p : q;
            int qq = p < q ? q : p;
            int idx = pp * 9 - (pp * (pp - 1)) / 2 + (qq - pp);
            ex2 += wd[p] * wd[q] * Cm[idx];
        }
    }
    ex2 /= N;

    double var = ex2 - mean * mean;
    double rinv = 1.0 / sqrt(var + 1e-5);
    float sc = (float)((double)gamma * rinv);
    float bi = (float)((double)beta - mean * (double)gamma * rinv);
    if (a < 0) g_sb1[f] = make_float2(sc, bi);
    else       g_sb2[a][f] = make_float2(sc, bi);
}

// ---------------------------------------------------------------------------
// Kernel 4: fused conv -> BN -> relu -> min -> FC dot.
// 4 batch rows per block packed as two f32x2 lanes; f-loop outer so conv
// weights / fcn weights are loaded once per f for all 4 rows.
// ---------------------------------------------------------------------------
__global__ void __launch_bounds__(128) main_kernel(
    const int* __restrict__ xb,
    const float* __restrict__ er, const float* __restrict__ ee, const float* __restrict__ et,
    const float* __restrict__ c1w, const float* __restrict__ c2w,
    const float* __restrict__ fcn_w, const float* __restrict__ fcn_b,
    float* __restrict__ out, int B)
{
    __shared__ float rows[GB][9][EDIM];
    __shared__ __align__(16) float w1s[FCH][12];
    __shared__ __align__(16) float w2s[FCH][12];
    __shared__ float2 sb1[FCH];
    __shared__ float2 sb2[A2][FCH];
    __shared__ const float* rp[GB][9];
    __shared__ float red[4][GB];

    int tid = threadIdx.x;
    int b0 = blockIdx.x * GB;

    if (tid < GB * 9) {
        int g = tid / 9, r = tid % 9;
        int b = b0 + g;
        const float* p = ee;  // harmless dummy for OOB rows
        if (b < B) {
            const int* x = xb + (size_t)b * NCOLS;
            switch (r) {
                case 0: p = ee + (size_t)x[1] * EDIM; break;
                case 1: p = er + (size_t)x[0] * EDIM; break;
                case 2: p = ee + (size_t)x[3] * EDIM; break;
                default: p = et + (size_t)x[r + 1] * EDIM; break;
            }
        }
        rp[g][r] = p;
    }
    __syncthreads();

    for (int i = tid; i < GB * 9 * EDIM; i += 128) {
        int g = i / (9 * EDIM);
        int rem = i % (9 * EDIM);
        int r = rem >> 7, c = rem & 127;
        rows[g][r][c] = __ldg(rp[g][r] + c);
    }
    for (int i = tid; i < FCH * 9; i += 128) {
        w1s[i / 9][i % 9] = c1w[i];
        w2s[i / 9][i % 9] = c2w[i];
    }
    if (tid < FCH) sb1[tid] = g_sb1[tid];
    for (int i = tid; i < A2 * FCH; i += 128) sb2[i / FCH][i % FCH] = g_sb2[i / FCH][i % FCH];
    __syncthreads();

    int w = tid;
    int wl = (w < WW) ? w : (WW - 1);   // clamp; out-of-range lanes masked later

    // packed register windows: pair P=0 -> rows (g0,g1), P=1 -> (g2,g3)
    u64 win[2][9][3];
    #pragma unroll
    for (int P = 0; P < 2; P++)
        #pragma unroll
        for (int r = 0; r < 9; r++)
            #pragma unroll
            for (int j = 0; j < 3; j++)
                win[P][r][j] = pk(rows[2 * P][r][wl + j], rows[2 * P + 1][r][wl + j]);

    float acc[GB] = {0.f, 0.f, 0.f, 0.f};
    const float* fcn1 = fcn_w;
    const float* fcn2 = fcn_w + FCH * WW;

    #pragma unroll 2
    for (int f = 0; f < FCH; f++) {
        const float4* p1 = (const float4*)&w1s[f][0];
        float4 Aw = p1[0], Bw = p1[1];
        float w8 = w1s[f][8];
        u64 k0 = pk(Aw.x, Aw.x), k1 = pk(Aw.y, Aw.y), k2 = pk(Aw.z, Aw.z);
        u64 k3 = pk(Aw.w, Aw.w), k4 = pk(Bw.x, Bw.x), k5 = pk(Bw.y, Bw.y);
        u64 k6 = pk(Bw.z, Bw.z), k7 = pk(Bw.w, Bw.w), k8 = pk(w8, w8);
        float2 sA = sb1[f];
        u64 s1 = pk(sA.x, sA.x), b1 = pk(sA.y, sA.y);
        float fw1 = __ldg(&fcn1[f * WW + wl]);
        float fw2 = __ldg(&fcn2[f * WW + wl]);

        const float4* p2 = (const float4*)&w2s[f][0];
        float4 Cw = p2[0], Dw = p2[1];
        float q8 = w2s[f][8];
        u64 q0 = pk(Cw.x, Cw.x), q1 = pk(Cw.y, Cw.y), q2 = pk(Cw.z, Cw.z);
        u64 q3 = pk(Cw.w, Cw.w), q4 = pk(Dw.x, Dw.x), q5 = pk(Dw.y, Dw.y);
        u64 q6 = pk(Dw.z, Dw.z), q7 = pk(Dw.w, Dw.w), q8p = pk(q8, q8);
        u64 s2[A2], b2[A2];
        #pragma unroll
        for (int a = 0; a < A2; a++) {
            float2 sB = sb2[a][f];
            s2[a] = pk(sB.x, sB.x);
            b2[a] = pk(sB.y, sB.y);
        }

        #pragma unroll
        for (int P = 0; P < 2; P++) {
            // conv1 over (E0, R, E1)
            u64 c = mul2(k0, win[P][0][0]);
            c = fma2(k1, win[P][0][1], c);
            c = fma2(k2, win[P][0][2], c);
            c = fma2(k3, win[P][1][0], c);
            c = fma2(k4, win[P][1][1], c);
            c = fma2(k5, win[P][1][2], c);
            c = fma2(k6, win[P][2][0], c);
            c = fma2(k7, win[P][2][1], c);
            c = fma2(k8, win[P][2][2], c);
            u64 v1 = fma2(c, s1, b1);
            float va, vb; upk(v1, va, vb);
            acc[2 * P]     = fmaf(fmaxf(va, 0.f), fw1, acc[2 * P]);
            acc[2 * P + 1] = fmaf(fmaxf(vb, 0.f), fw1, acc[2 * P + 1]);

            // conv2: shared R taps once, then 3 arity slots
            u64 rpart = mul2(q3, win[P][1][0]);
            rpart = fma2(q4, win[P][1][1], rpart);
            rpart = fma2(q5, win[P][1][2], rpart);

            u64 u[A2];
            #pragma unroll
            for (int a = 0; a < A2; a++) {
                int rh = 3 + 2 * a, rt2 = 4 + 2 * a;
                u64 t = fma2(q0, win[P][rh][0], rpart);
                t = fma2(q1, win[P][rh][1], t);
                t = fma2(q2, win[P][rh][2], t);
                t = fma2(q6, win[P][rt2][0], t);
                t = fma2(q7, win[P][rt2][1], t);
                t = fma2(q8p, win[P][rt2][2], t);
                u[a] = fma2(t, s2[a], b2[a]);
            }
            float u0a, u0b, u1a, u1b, u2a, u2b;
            upk(u[0], u0a, u0b); upk(u[1], u1a, u1b); upk(u[2], u2a, u2b);
            float ma = fminf(fminf(u0a, u1a), u2a);
            float mb = fminf(fminf(u0b, u1b), u2b);
            acc[2 * P]     = fmaf(fmaxf(ma, 0.f), fw2, acc[2 * P]);
            acc[2 * P + 1] = fmaf(fmaxf(mb, 0.f), fw2, acc[2 * P + 1]);
        }
    }

    if (w >= WW) {
        #pragma unroll
        for (int g = 0; g < GB; g++) acc[g] = 0.f;
    }

    // block reduction
    int lane = tid & 31, warp = tid >> 5;
    #pragma unroll
    for (int g = 0; g < GB; g++) {
        float v = acc[g];
        #pragma unroll
        for (int off = 16; off; off >>= 1) v += __shfl_down_sync(0xffffffffu, v, off);
        if (lane == 0) red[warp][g] = v;
    }
    __syncthreads();
    if (tid < GB && b0 + tid < B) {
        float tot = red[0][tid] + red[1][tid] + red[2][tid] + red[3][tid] + __ldg(&fcn_b[0]);
        out[b0 + tid] = tot;
    }
}

// ---------------------------------------------------------------------------
// Launch: stats -> reduce -> finalize -> main (all graph-capturable)
// ---------------------------------------------------------------------------
extern "C" void kernel_launch(void* const* d_in, const int* in_sizes, int n_in,
                              void* d_out, int out_size)
{
    const int*   xb  = (const int*)d_in[0];
    const float* er  = (const float*)d_in[3];
    const float* ee  = (const float*)d_in[4];
    const float* et  = (const float*)d_in[5];
    const float* c1w = (const float*)d_in[6];
    const float* g1  = (const float*)d_in[8];
    const float* be1 = (const float*)d_in[9];
    const float* c2w = (const float*)d_in[10];
    const float* g2  = (const float*)d_in[12];
    const float* be2 = (const float*)d_in[13];
    const float* fw  = (const float*)d_in[14];
    const float* fb  = (const float*)d_in[15];

    int B = in_sizes[0] / NCOLS;
    int sblocks = (B + SR - 1) / SR;
    if (sblocks * 2 > MAXPART) sblocks = MAXPART / 2;   // safety clamp (B<=8192)
    int nparts = sblocks * 2;

    stats_kernel<<<sblocks, 256>>>(xb, er, ee, et, B);
    reduce_kernel<<<1, 256>>>(nparts);
    finalize_kernel<<<1, 256>>>(c1w, g1, be1, c2w, g2, be2, B);
    main_kernel<<<(B + GB - 1) / GB, 128>>>(xb, er, ee, et, c1w, c2w, fw, fb,
                                            (float*)d_out, B);
}

// round 4
// speedup vs baseline: 2.0292x; 1.2435x over previous
#include <cuda_runtime.h>
#include <math.h>

// Problem constants
#define EDIM 128
#define FCH  64
#define WW   126           // EDIM - 2
#define A2   3
#define NCOLS 10
#define NTASK 216          // 45 C + 9 S per branch, 4 branches
#define SR   16            // batch rows per stats block
#define NPART 512

typedef unsigned long long u64;

// ---- f32x2 packed helpers ----
__device__ __forceinline__ u64 pk(float a, float b) {
    u64 d; asm("mov.b64 %0, {%1,%2};" : "=l"(d) : "f"(a), "f"(b)); return d;
}
__device__ __forceinline__ void upk(u64 d, float& a, float& b) {
    asm("mov.b64 {%0,%1}, %2;" : "=f"(a), "=f"(b) : "l"(d));
}
__device__ __forceinline__ u64 fma2(u64 a, u64 b, u64 c) {
    u64 d; asm("fma.rn.f32x2 %0, %1, %2, %3;" : "=l"(d) : "l"(a), "l"(b), "l"(c)); return d;
}
__device__ __forceinline__ u64 mul2(u64 a, u64 b) {
    u64 d; asm("mul.rn.f32x2 %0, %1, %2;" : "=l"(d) : "l"(a), "l"(b)); return d;
}

// Global scratch
__device__ float g_part[NPART][NTASK];
__device__ u64   g_w1p[FCH][9];   // conv1 weights * bn1 scale, dup-packed
__device__ u64   g_b1p[FCH];      // bn1 bias, dup-packed
__device__ u64   g_w2p[FCH][9];   // conv2 weights, dup-packed
__device__ u64   g_s2p[A2][FCH];  // bn2 scale, dup-packed
__device__ u64   g_b2p[A2][FCH];  // bn2 bias, dup-packed
__device__ float g_fcnT[2][WW][FCH];  // transposed FC weights

// ---------------------------------------------------------------------------
// Kernel 1: tap sums S / correlations C. 16 rows/block, double-buffered smem.
// 8 warps: warp -> (branch wq = warp&3, w-half = warp>>2).
// ---------------------------------------------------------------------------
__global__ void __launch_bounds__(256) stats_kernel(
    const int* __restrict__ xb,
    const float* __restrict__ er,
    const float* __restrict__ ee,
    const float* __restrict__ et,
    int B)
{
    __shared__ float s[2][9][EDIM];
    __shared__ const float* rp[SR][9];

    int tid = threadIdx.x;
    int warp = tid >> 5, lane = tid & 31;
    int wq = warp & 3, whalf = warp >> 2;
    int b0 = blockIdx.x * SR;

    for (int i = tid; i < SR * 9; i += 256) {
        int g = i / 9, r = i % 9;
        int b = b0 + g;
        const float* p;
        if (b < B) {
            const int* x = xb + (size_t)b * NCOLS;
            switch (r) {
                case 0: p = ee + (size_t)x[1] * EDIM; break;
                case 1: p = er + (size_t)x[0] * EDIM; break;
                case 2: p = ee + (size_t)x[3] * EDIM; break;
                default: p = et + (size_t)x[r + 1] * EDIM; break;
            }
        } else {
            p = (r == 0 || r == 2) ? ee : (r == 1 ? er : et);  // row 0 = zeros
        }
        rp[g][r] = p;
    }

    int rt = (wq == 0) ? 0 : 2 * wq + 1;
    int rb = (wq == 0) ? 2 : 2 * wq + 2;

    float facc[54];
    #pragma unroll
    for (int k = 0; k < 54; k++) facc[k] = 0.f;

    __syncthreads();
    // preload row-set 0 into buffer 0
    for (int i = tid; i < 9 * EDIM; i += 256) {
        int r = i >> 7, c = i & 127;
        s[0][r][c] = __ldg(rp[0][r] + c);
    }
    __syncthreads();

    for (int g = 0; g < SR; g++) {
        int buf = g & 1;
        // prefetch next row-set into registers
        float pre[5];
        if (g + 1 < SR) {
            #pragma unroll
            for (int k = 0; k < 5; k++) {
                int i = tid + 256 * k;
                if (i < 9 * EDIM) pre[k] = __ldg(rp[g + 1][i >> 7] + (i & 127));
            }
        }
        // compute on current buffer
        #pragma unroll
        for (int ch = 0; ch < 2; ch++) {
            int w = whalf * 64 + ch * 32 + lane;
            if (w < WW) {
                float v[9];
                #pragma unroll
                for (int j = 0; j < 3; j++) {
                    v[j]     = s[buf][rt][w + j];
                    v[3 + j] = s[buf][1][w + j];
                    v[6 + j] = s[buf][rb][w + j];
                }
                int idx = 0;
                #pragma unroll
                for (int p = 0; p < 9; p++) {
                    facc[45 + p] += v[p];
                    #pragma unroll
                    for (int q = p; q < 9; q++) { facc[idx] += v[p] * v[q]; idx++; }
                }
            }
        }
        __syncthreads();
        if (g + 1 < SR) {
            #pragma unroll
            for (int k = 0; k < 5; k++) {
                int i = tid + 256 * k;
                if (i < 9 * EDIM) s[1 - buf][i >> 7][i & 127] = pre[k];
            }
        }
        __syncthreads();
    }

    #pragma unroll
    for (int k = 0; k < 54; k++) {
        float v = facc[k];
        #pragma unroll
        for (int off = 16; off; off >>= 1) v += __shfl_down_sync(0xffffffffu, v, off);
        facc[k] = v;
    }
    if (lane == 0) {
        int part = blockIdx.x * 2 + whalf;
        #pragma unroll
        for (int k = 0; k < 54; k++) g_part[part][wq * 54 + k] = facc[k];
    }
}

// ---------------------------------------------------------------------------
// Kernel 2: reduce partials -> BN params -> packed weight tables (merged).
// One block, 256 threads.
// ---------------------------------------------------------------------------
__global__ void __launch_bounds__(256) redfin_kernel(
    const float* __restrict__ c1w, const float* __restrict__ g1, const float* __restrict__ be1,
    const float* __restrict__ c2w, const float* __restrict__ g2, const float* __restrict__ be2,
    int B, int nparts)
{
    __shared__ double sacc[NTASK];
    __shared__ float2 ssb[256];

    int t = threadIdx.x;

    if (t < NTASK) {
        double a0 = 0, a1 = 0, a2 = 0, a3 = 0, a4 = 0, a5 = 0, a6 = 0, a7 = 0;
        int p = 0;
        for (; p + 8 <= nparts; p += 8) {
            a0 += (double)g_part[p][t];     a1 += (double)g_part[p + 1][t];
            a2 += (double)g_part[p + 2][t]; a3 += (double)g_part[p + 3][t];
            a4 += (double)g_part[p + 4][t]; a5 += (double)g_part[p + 5][t];
            a6 += (double)g_part[p + 6][t]; a7 += (double)g_part[p + 7][t];
        }
        for (; p < nparts; p++) a0 += (double)g_part[p][t];
        sacc[t] = ((a0 + a1) + (a2 + a3)) + ((a4 + a5) + (a6 + a7));
    }
    __syncthreads();

    // finalize BN scale/bias per (branch, channel)
    {
        double N = (double)B * (double)WW;
        const double* Cm; const double* Sm; const float* wf;
        float gamma, beta;
        if (t < FCH) {
            Cm = sacc; Sm = sacc + 45;
            wf = c1w + t * 9; gamma = g1[t]; beta = be1[t];
        } else {
            int u = t - FCH; int a = u / FCH, f = u % FCH;
            const double* base = sacc + 54 + a * 54;
            Cm = base; Sm = base + 45;
            wf = c2w + f * 9; gamma = g2[f]; beta = be2[f];
        }
        double wd[9];
        #pragma unroll
        for (int p = 0; p < 9; p++) wd[p] = (double)wf[p];
        double mean = 0.0;
        #pragma unroll
        for (int p = 0; p < 9; p++) mean += wd[p] * Sm[p];
        mean /= N;
        double ex2 = 0.0;
        #pragma unroll
        for (int p = 0; p < 9; p++) {
            #pragma unroll
            for (int q = 0; q < 9; q++) {
                int pp = p < q ? p : q;
                int qq = p < q ? q : p;
                int idx = pp * 9 - (pp * (pp - 1)) / 2 + (qq - pp);
                ex2 += wd[p] * wd[q] * Cm[idx];
            }
        }
        ex2 /= N;
        double var = ex2 - mean * mean;
        double rinv = 1.0 / sqrt(var + 1e-5);
        float sc = (float)((double)gamma * rinv);
        float bi = (float)((double)beta - mean * (double)gamma * rinv);
        ssb[t] = make_float2(sc, bi);
    }
    __syncthreads();

    // pack duplicated-pair weight tables
    if (t < FCH) {
        float s1 = ssb[t].x, b1 = ssb[t].y;
        #pragma unroll
        for (int j = 0; j < 9; j++) {
            float w1 = c1w[t * 9 + j] * s1;
            g_w1p[t][j] = pk(w1, w1);
            float w2 = c2w[t * 9 + j];
            g_w2p[t][j] = pk(w2, w2);
        }
        g_b1p[t] = pk(b1, b1);
    } else {
        int u = t - FCH; int a = u / FCH, f = u % FCH;
        g_s2p[a][f] = pk(ssb[t].x, ssb[t].x);
        g_b2p[a][f] = pk(ssb[t].y, ssb[t].y);
    }
}

// ---------------------------------------------------------------------------
// Kernel 3: transpose fcn weights to [half][w][f] for coalesced access
// ---------------------------------------------------------------------------
__global__ void fcnT_kernel(const float* __restrict__ fcn_w) {
    int w = blockIdx.x, h = blockIdx.y, f = threadIdx.x;
    g_fcnT[h][w][f] = fcn_w[h * FCH * WW + f * WW + w];
}

// ---------------------------------------------------------------------------
// Kernel 4: fused conv -> BN -> relu -> min -> FC dot.
// Thread = (channel f = tid&63, batch-pair gp = tid>>6). 4 batch rows/block.
// Weights live in registers (loaded once); windows slide via unroll-3 rotation;
// window LDS are warp-broadcast (all lanes same address).
// ---------------------------------------------------------------------------
__global__ void __launch_bounds__(128, 4) main_kernel(
    const int* __restrict__ xb,
    const float* __restrict__ er, const float* __restrict__ ee, const float* __restrict__ et,
    const float* __restrict__ fcn_b,
    float* __restrict__ out, int B)
{
    __shared__ u64 rows_pk[2][9][EDIM];   // (g0,g1)-packed embedding rows, 18KB
    __shared__ const float* rp[4][9];
    __shared__ float red[4][2];

    int tid = threadIdx.x;
    int f = tid & 63, gp = tid >> 6;
    int b0 = blockIdx.x * 4;

    if (tid < 36) {
        int g = tid / 9, r = tid % 9;
        int b = b0 + g;
        const float* p;
        if (b < B) {
            const int* x = xb + (size_t)b * NCOLS;
            switch (r) {
                case 0: p = ee + (size_t)x[1] * EDIM; break;
                case 1: p = er + (size_t)x[0] * EDIM; break;
                case 2: p = ee + (size_t)x[3] * EDIM; break;
                default: p = et + (size_t)x[r + 1] * EDIM; break;
            }
        } else {
            p = (r == 0 || r == 2) ? ee : (r == 1 ? er : et);  // row 0 = zeros
        }
        rp[g][r] = p;
    }
    __syncthreads();

    // gather + pair-pack embedding rows into smem
    for (int i = tid; i < 2 * 9 * EDIM; i += 128) {
        int gq = i / (9 * EDIM);
        int rem = i % (9 * EDIM);
        int r = rem >> 7, c = rem & 127;
        float a = __ldg(rp[2 * gq][r] + c);
        float b = __ldg(rp[2 * gq + 1][r] + c);
        rows_pk[gq][r][c] = pk(a, b);
    }

    // per-thread weights (25 u64, loaded once)
    u64 W1[9], W2[9], B1, S2[A2], B2[A2];
    #pragma unroll
    for (int j = 0; j < 9; j++) { W1[j] = g_w1p[f][j]; W2[j] = g_w2p[f][j]; }
    B1 = g_b1p[f];
    #pragma unroll
    for (int a = 0; a < A2; a++) { S2[a] = g_s2p[a][f]; B2[a] = g_b2p[a][f]; }
    __syncthreads();

    const float* fp1 = &g_fcnT[0][0][f];
    const float* fp2 = &g_fcnT[1][0][f];
    float acc0 = 0.f, acc1 = 0.f;

    u64 Wa[9], Wb[9], Wc[9];
    #pragma unroll
    for (int r = 0; r < 9; r++) {
        Wa[r] = rows_pk[gp][r][0];
        Wb[r] = rows_pk[gp][r][1];
    }

    #define STEP(A_, B_, C_, wv)                                              \
    {                                                                         \
        _Pragma("unroll")                                                     \
        for (int r = 0; r < 9; r++) C_[r] = rows_pk[gp][r][(wv) + 2];         \
        u64 c1 = fma2(W1[0], A_[0], B1);                                      \
        c1 = fma2(W1[1], B_[0], c1);                                          \
        c1 = fma2(W1[2], C_[0], c1);                                          \
        c1 = fma2(W1[3], A_[1], c1);                                          \
        c1 = fma2(W1[4], B_[1], c1);                                          \
        c1 = fma2(W1[5], C_[1], c1);                                          \
        c1 = fma2(W1[6], A_[2], c1);                                          \
        c1 = fma2(W1[7], B_[2], c1);                                          \
        c1 = fma2(W1[8], C_[2], c1);                                          \
        float va, vb; upk(c1, va, vb);                                        \
        float fw1 = __ldg(fp1 + (wv) * FCH);                                  \
        acc0 = fmaf(fmaxf(va, 0.f), fw1, acc0);                               \
        acc1 = fmaf(fmaxf(vb, 0.f), fw1, acc1);                               \
        u64 rpt = mul2(W2[3], A_[1]);                                         \
        rpt = fma2(W2[4], B_[1], rpt);                                        \
        rpt = fma2(W2[5], C_[1], rpt);                                        \
        u64 u0, u1, u2;                                                       \
        {                                                                     \
            u64 t = fma2(W2[0], A_[3], rpt);                                  \
            t = fma2(W2[1], B_[3], t);  t = fma2(W2[2], C_[3], t);            \
            t = fma2(W2[6], A_[4], t);  t = fma2(W2[7], B_[4], t);            \
            t = fma2(W2[8], C_[4], t);                                        \
            u0 = fma2(t, S2[0], B2[0]);                                       \
        }                                                                     \
        {                                                                     \
            u64 t = fma2(W2[0], A_[5], rpt);                                  \
            t = fma2(W2[1], B_[5], t);  t = fma2(W2[2], C_[5], t);            \
            t = fma2(W2[6], A_[6], t);  t = fma2(W2[7], B_[6], t);            \
            t = fma2(W2[8], C_[6], t);                                        \
            u1 = fma2(t, S2[1], B2[1]);                                       \
        }                                                                     \
        {                                                                     \
            u64 t = fma2(W2[0], A_[7], rpt);                                  \
            t = fma2(W2[1], B_[7], t);  t = fma2(W2[2], C_[7], t);            \
            t = fma2(W2[6], A_[8], t);  t = fma2(W2[7], B_[8], t);            \
            t = fma2(W2[8], C_[8], t);                                        \
            u2 = fma2(t, S2[2], B2[2]);                                       \
        }                                                                     \
        float x0, y0, x1, y1, x2, y2;                                         \
        upk(u0, x0, y0); upk(u1, x1, y1); upk(u2, x2, y2);                    \
        float ma = fminf(fminf(x0, x1), x2);                                  \
        float mb = fminf(fminf(y0, y1), y2);                                  \
        float fw2 = __ldg(fp2 + (wv) * FCH);                                  \
        acc0 = fmaf(fmaxf(ma, 0.f), fw2, acc0);                               \
        acc1 = fmaf(fmaxf(mb, 0.f), fw2, acc1);                               \
    }

    for (int w = 0; w < WW; w += 3) {
        STEP(Wa, Wb, Wc, w);
        STEP(Wb, Wc, Wa, w + 1);
        STEP(Wc, Wa, Wb, w + 2);
    }
    #undef STEP

    // reduce over f (within each gp's two warps)
    int lane = tid & 31, warp = tid >> 5;
    #pragma unroll
    for (int off = 16; off; off >>= 1) {
        acc0 += __shfl_down_sync(0xffffffffu, acc0, off);
        acc1 += __shfl_down_sync(0xffffffffu, acc1, off);
    }
    if (lane == 0) { red[warp][0] = acc0; red[warp][1] = acc1; }
    __syncthreads();
    if (tid < 4) {
        int g = tid;                 // row b0+g
        int gq = g >> 1, h = g & 1;  // pair gq, half h
        float tot = red[2 * gq][h] + red[2 * gq + 1][h] + __ldg(&fcn_b[0]);
        if (b0 + g < B) out[b0 + g] = tot;
    }
}

// ---------------------------------------------------------------------------
// Launch: stats -> redfin -> fcnT -> main
// ---------------------------------------------------------------------------
extern "C" void kernel_launch(void* const* d_in, const int* in_sizes, int n_in,
                              void* d_out, int out_size)
{
    const int*   xb  = (const int*)d_in[0];
    const float* er  = (const float*)d_in[3];
    const float* ee  = (const float*)d_in[4];
    const float* et  = (const float*)d_in[5];
    const float* c1w = (const float*)d_in[6];
    const float* g1  = (const float*)d_in[8];
    const float* be1 = (const float*)d_in[9];
    const float* c2w = (const float*)d_in[10];
    const float* g2  = (const float*)d_in[12];
    const float* be2 = (const float*)d_in[13];
    const float* fw  = (const float*)d_in[14];
    const float* fb  = (const float*)d_in[15];

    int B = in_sizes[0] / NCOLS;
    int sblocks = (B + SR - 1) / SR;
    if (sblocks * 2 > NPART) sblocks = NPART / 2;
    int nparts = sblocks * 2;

    stats_kernel<<<sblocks, 256>>>(xb, er, ee, et, B);
    redfin_kernel<<<1, 256>>>(c1w, g1, be1, c2w, g2, be2, B, nparts);
    fcnT_kernel<<<dim3(WW, 2), FCH>>>(fw);
    main_kernel<<<(B + 3) / 4, 128>>>(xb, er, ee, et, fb, (float*)d_out, B);
}